// round 14
// baseline (speedup 1.0000x reference)
#include <cuda_runtime.h>

// Problem constants (fixed by reference setup_inputs)
#define Hh     32
#define EPB    2          // batch elements per block
#define TIN    999        // teacher-forced steps
#define STEPS  1999       // TIN + future(1000)
#define BATCH  1024

typedef unsigned long long u64;

// Scratch: h2 history for the TF phase (head applied by head_kernel) ~131 MB
__device__ float H2g[(size_t)BATCH * TIN * Hh];

// Packed 2xfp32 FMA / ADD (sm_103a f32x2 pipe)
__device__ __forceinline__ u64 fma2(u64 a, u64 b, u64 c) {
    u64 d;
    asm("fma.rn.f32x2 %0, %1, %2, %3;" : "=l"(d) : "l"(a), "l"(b), "l"(c));
    return d;
}
__device__ __forceinline__ u64 add2(u64 a, u64 b) {
    u64 d;
    asm("add.rn.f32x2 %0, %1, %2;" : "=l"(d) : "l"(a), "l"(b));
    return d;
}
__device__ __forceinline__ float f2lo(u64 a) { return __uint_as_float((unsigned)a); }
__device__ __forceinline__ float f2hi(u64 a) { return __uint_as_float((unsigned)(a >> 32)); }

__device__ __forceinline__ float ex2a(float x) { float y; asm("ex2.approx.f32 %0, %1;" : "=f"(y) : "f"(x)); return y; }
__device__ __forceinline__ float rcpa(float x) { float y; asm("rcp.approx.f32 %0, %1;" : "=f"(y) : "f"(x)); return y; }

// sigmoid(x) = 1/(1 + 2^(-x*log2e)); ~1e-7 accurate
__device__ __forceinline__ float sigm(float x) {
    return rcpa(1.0f + ex2a(-1.4426950408889634f * x));
}
// tanh(x) = 1 - 2/(1 + 2^(2x*log2e)); ~1e-7 accurate
__device__ __forceinline__ float tanh_(float x) {
    return fmaf(-2.0f, rcpa(1.0f + ex2a(2.8853900817779268f * x)), 1.0f);
}

__global__ __launch_bounds__(128, 4) void lstm_seq_kernel(
    const float* __restrict__ input,                                   // [B, TIN]
    const float* __restrict__ W_ih1, const float* __restrict__ W_hh1,  // [4H,1], [4H,H]
    const float* __restrict__ b_ih1, const float* __restrict__ b_hh1,  // [4H]
    const float* __restrict__ W_ih2, const float* __restrict__ W_hh2,  // [4H,H], [4H,H]
    const float* __restrict__ b_ih2, const float* __restrict__ b_hh2,  // [4H]
    const float* __restrict__ W_lin, const float* __restrict__ b_lin,  // [1,H], [1]
    float* __restrict__ out)                                           // [B, STEPS]
{
    __shared__ float sh_in[EPB][TIN];                       // staged input rows (~8KB)
    __shared__ __align__(16) float sh_h1[EPB][Hh];
    __shared__ __align__(16) float sh_h2[EPB][Hh];
    __shared__ float sh_zA[EPB][4 * Hh];                    // layer-1 pre-activations
    __shared__ float sh_zB[EPB][4 * Hh];                    // layer-2 pre-activations
    __shared__ __align__(16) float sh_wl[Hh];               // W_lin copy
    __shared__ float sh_wih1[4 * Hh];                       // W_ih1 copy (gen x-fold)

    const int r    = threadIdx.x;        // gate row 0..127
    const int lane = r & 31;
    const int w    = r >> 5;
    const int b0   = blockIdx.x * EPB;

    const bool is1 = (w < 2);            // warps 0-1: L1-combine (own c1); 2-3: L2 (own c2)
    const int  ce  = is1 ? w : (w - 2);  // element owned in combine phase
    const int  cj  = lane;               // hidden unit owned

    // ---- Weights into registers (packed pairs along k) ----
    const float wih1 = W_ih1[r];
    const float bb1  = b_ih1[r] + b_hh1[r];
    const float bb2  = b_ih2[r] + b_hh2[r];
    const float blin = b_lin[0];

    u64 whh1p[Hh / 2], wih2p[Hh / 2], whh2p[Hh / 2];
    {
        const u64* p1 = (const u64*)(W_hh1 + r * Hh);  // rows are 128B -> 8B aligned
        const u64* p2 = (const u64*)(W_ih2 + r * Hh);
        const u64* p3 = (const u64*)(W_hh2 + r * Hh);
#pragma unroll
        for (int i = 0; i < Hh / 2; i++) { whh1p[i] = p1[i]; wih2p[i] = p2[i]; whh2p[i] = p3[i]; }
    }

    // ---- Stage input rows + weight copies into SMEM ----
#pragma unroll
    for (int e = 0; e < EPB; e++)
        for (int t = r; t < TIN; t += 128)
            sh_in[e][t] = input[(b0 + e) * TIN + t];
    if (r < Hh) sh_wl[r] = W_lin[r];
    sh_wih1[r] = wih1;

    if (is1) sh_h1[ce][cj] = 0.0f;
    else     sh_h2[ce][cj] = 0.0f;
    float cst = 0.0f;                    // c1 (w0-1) or c2 (w2-3) of (ce,cj)
    __syncthreads();

    // ---- phase helpers ----
#define DOT_Z1(e, xval) do {                                              \
        const ulonglong2* hp = (const ulonglong2*)sh_h1[e];               \
        u64 a0 = 0ull, a1 = 0ull;                                         \
        _Pragma("unroll")                                                 \
        for (int i = 0; i < 8; i++) {                                     \
            ulonglong2 hv = hp[i];                                        \
            a0 = fma2(whh1p[2 * i],     hv.x, a0);                        \
            a1 = fma2(whh1p[2 * i + 1], hv.y, a1);                        \
        }                                                                 \
        u64 s = add2(a0, a1);                                             \
        sh_zA[e][r] = fmaf(wih1, (xval), bb1) + (f2lo(s) + f2hi(s));      \
    } while (0)

#define DOT_Z2(e) do {                                                    \
        const ulonglong2* h1p = (const ulonglong2*)sh_h1[e];              \
        const ulonglong2* h2p = (const ulonglong2*)sh_h2[e];              \
        u64 a0 = 0ull, a1 = 0ull, a2 = 0ull, a3 = 0ull;                   \
        _Pragma("unroll")                                                 \
        for (int i = 0; i < 8; i++) {                                     \
            ulonglong2 hv1 = h1p[i];                                      \
            ulonglong2 hv2 = h2p[i];                                      \
            a0 = fma2(wih2p[2 * i],     hv1.x, a0);                       \
            a1 = fma2(wih2p[2 * i + 1], hv1.y, a1);                       \
            a2 = fma2(whh2p[2 * i],     hv2.x, a2);                       \
            a3 = fma2(whh2p[2 * i + 1], hv2.y, a3);                       \
        }                                                                 \
        u64 s = add2(add2(a0, a1), add2(a2, a3));                         \
        sh_zB[e][r] = bb2 + (f2lo(s) + f2hi(s));                          \
    } while (0)

#define COMBINE_L1() do {                                                 \
        float zi = sh_zA[ce][cj],          zf = sh_zA[ce][Hh + cj];       \
        float zg = sh_zA[ce][2 * Hh + cj], zo = sh_zA[ce][3 * Hh + cj];   \
        float cn = fmaf(sigm(zf), cst, sigm(zi) * tanh_(zg));             \
        cst = cn;                                                         \
        sh_h1[ce][cj] = sigm(zo) * tanh_(cn);                             \
    } while (0)

#define COMBINE_L2(tstore) do {                                           \
        float zi = sh_zB[ce][cj],          zf = sh_zB[ce][Hh + cj];       \
        float zg = sh_zB[ce][2 * Hh + cj], zo = sh_zB[ce][3 * Hh + cj];   \
        float cn = fmaf(sigm(zf), cst, sigm(zi) * tanh_(zg));             \
        cst = cn;                                                         \
        float hn = sigm(zo) * tanh_(cn);                                  \
        sh_h2[ce][cj] = hn;                                               \
        H2g[((size_t)(b0 + ce) * TIN + (tstore)) * Hh + cj] = hn;         \
    } while (0)

    // ========== Teacher-forced phase: 2-layer time pipeline, 2 barriers/step ==========
    // X(k): z1(k) [reads h1(k-1), x(k)] and z2(k-1) [reads h1(k-1), h2(k-2)].
    // Y(k): combine-L1(k) on w0-1  ∥  combine-L2(k-1) on w2-3.
    // Prologue k=0
    DOT_Z1(0, sh_in[0][0]);
    DOT_Z1(1, sh_in[1][0]);
    __syncthreads();                     // A
    if (is1) COMBINE_L1();
    __syncthreads();                     // B

#pragma unroll 1
    for (int k = 1; k < TIN; k++) {
        // X: element-sequential dots (keeps transient accumulators small)
        DOT_Z2(0);
        DOT_Z2(1);
        DOT_Z1(0, sh_in[0][k]);
        DOT_Z1(1, sh_in[1][k]);
        __syncthreads();                 // A

        // Y: both combines in parallel on disjoint warp pairs
        if (is1) COMBINE_L1();
        else     COMBINE_L2(k - 1);
        __syncthreads();                 // B
    }

    // Epilogue: finish L2 of step TIN-1
    DOT_Z2(0);
    DOT_Z2(1);
    __syncthreads();                     // A
    if (!is1) COMBINE_L2(TIN - 1);
    __syncthreads();                     // B

    // ========== Gen phase: 3 barriers/step, feedback recomputed in P2 (proven) ==========
#pragma unroll 1
    for (int t = TIN; t < STEPS; t++) {
        // P1: x-independent hh1 partial
#pragma unroll
        for (int e = 0; e < EPB; e++) {
            const ulonglong2* hp = (const ulonglong2*)sh_h1[e];
            u64 a0 = 0ull, a1 = 0ull;
#pragma unroll
            for (int i = 0; i < 8; i++) {
                ulonglong2 hv = hp[i];
                a0 = fma2(whh1p[2 * i],     hv.x, a0);
                a1 = fma2(whh1p[2 * i + 1], hv.y, a1);
            }
            u64 s = add2(a0, a1);
            sh_zA[e][r] = bb1 + (f2lo(s) + f2hi(s));
        }
        __syncthreads();                 // A: z1-partials ready; h2(t-1) final

        // P2 (w0-1): x = W_lin@h2(t-1)+b, emit out[t-1], fold, combine L1
        if (is1) {
            const ulonglong2* wp = (const ulonglong2*)sh_wl;
            const ulonglong2* hp = (const ulonglong2*)sh_h2[ce];
            u64 a0 = 0ull, a1 = 0ull;
#pragma unroll
            for (int i = 0; i < 8; i++) {
                ulonglong2 wv = wp[i];
                ulonglong2 hv = hp[i];
                a0 = fma2(wv.x, hv.x, a0);
                a1 = fma2(wv.y, hv.y, a1);
            }
            u64 sx = add2(a0, a1);
            float x = (f2lo(sx) + f2hi(sx)) + blin;              // == out(t-1)
            if (cj == 0) out[(size_t)(b0 + ce) * STEPS + (t - 1)] = x;

            float zi = fmaf(sh_wih1[cj],          x, sh_zA[ce][cj]);
            float zf = fmaf(sh_wih1[Hh + cj],     x, sh_zA[ce][Hh + cj]);
            float zg = fmaf(sh_wih1[2 * Hh + cj], x, sh_zA[ce][2 * Hh + cj]);
            float zo = fmaf(sh_wih1[3 * Hh + cj], x, sh_zA[ce][3 * Hh + cj]);
            float cn = fmaf(sigm(zf), cst, sigm(zi) * tanh_(zg));
            cst = cn;
            sh_h1[ce][cj] = sigm(zo) * tanh_(cn);
        }
        __syncthreads();                 // B

        // P3: layer-2 dots
        DOT_Z2(0);
        DOT_Z2(1);
        __syncthreads();                 // C

        // P4 (w2-3): combine L2 -> h2(t); w0-1 flow into next P1
        if (!is1) {
            float zi = sh_zB[ce][cj],          zf = sh_zB[ce][Hh + cj];
            float zg = sh_zB[ce][2 * Hh + cj], zo = sh_zB[ce][3 * Hh + cj];
            float cn = fmaf(sigm(zf), cst, sigm(zi) * tanh_(zg));
            cst = cn;
            sh_h2[ce][cj] = sigm(zo) * tanh_(cn);
        }
    }

    // Final output: out[STEPS-1] = W_lin @ h2(final) + b_lin
    __syncthreads();
    if (is1 && cj == 0) {
        const ulonglong2* wp = (const ulonglong2*)sh_wl;
        const ulonglong2* hp = (const ulonglong2*)sh_h2[ce];
        u64 a0 = 0ull, a1 = 0ull;
#pragma unroll
        for (int i = 0; i < 8; i++) {
            ulonglong2 wv = wp[i];
            ulonglong2 hv = hp[i];
            a0 = fma2(wv.x, hv.x, a0);
            a1 = fma2(wv.y, hv.y, a1);
        }
        u64 sx = add2(a0, a1);
        out[(size_t)(b0 + ce) * STEPS + (STEPS - 1)] = (f2lo(sx) + f2hi(sx)) + blin;
    }
}

// Apply linear head to stored TF h2 history: out[b][t] = W_lin @ H2g[b][t] + b_lin
__global__ __launch_bounds__(256) void head_kernel(
    const float* __restrict__ W_lin, const float* __restrict__ b_lin,
    float* __restrict__ out)
{
    const int b = blockIdx.x;
    float4 wv[8];
    const float4* wp = (const float4*)W_lin;
#pragma unroll
    for (int i = 0; i < 8; i++) wv[i] = wp[i];
    const float bl = b_lin[0];

    for (int t = threadIdx.x; t < TIN; t += 256) {
        const float4* hp = (const float4*)(H2g + ((size_t)b * TIN + t) * Hh);
        float acc = bl;
#pragma unroll
        for (int i = 0; i < 8; i++) {
            float4 h = hp[i];
            acc += wv[i].x * h.x + wv[i].y * h.y + wv[i].z * h.z + wv[i].w * h.w;
        }
        out[(size_t)b * STEPS + t] = acc;
    }
}

extern "C" void kernel_launch(void* const* d_in, const int* in_sizes, int n_in,
                              void* d_out, int out_size) {
    const float* input = (const float*)d_in[0];
    const float* W_ih1 = (const float*)d_in[1];
    const float* W_hh1 = (const float*)d_in[2];
    const float* b_ih1 = (const float*)d_in[3];
    const float* b_hh1 = (const float*)d_in[4];
    const float* W_ih2 = (const float*)d_in[5];
    const float* W_hh2 = (const float*)d_in[6];
    const float* b_ih2 = (const float*)d_in[7];
    const float* b_hh2 = (const float*)d_in[8];
    const float* W_lin = (const float*)d_in[9];
    const float* b_lin = (const float*)d_in[10];
    float* out = (float*)d_out;

    lstm_seq_kernel<<<BATCH / EPB, 128>>>(input, W_ih1, W_hh1, b_ih1, b_hh1,
                                          W_ih2, W_hh2, b_ih2, b_hh2,
                                          W_lin, b_lin, out);
    head_kernel<<<BATCH, 256>>>(W_lin, b_lin, out);
}

// round 15
// speedup vs baseline: 1.6307x; 1.6307x over previous
#include <cuda_runtime.h>

// Problem constants (fixed by reference setup_inputs)
#define Hh     32
#define TIN    999        // teacher-forced steps
#define STEPS  1999       // TIN + future(1000)
#define BATCH  1024
#define G2     432        // blocks carrying 2 elements (bids 0..431)
#define GRID   592        // 4 blocks per SM on 148 SMs (wave-1 deterministic)

typedef unsigned long long u64;

// Scratch: h2 history for the TF phase (head applied by head_kernel) ~131 MB
__device__ float H2g[(size_t)BATCH * TIN * Hh];

// Packed 2xfp32 FMA / ADD (sm_103a f32x2 pipe)
__device__ __forceinline__ u64 fma2(u64 a, u64 b, u64 c) {
    u64 d;
    asm("fma.rn.f32x2 %0, %1, %2, %3;" : "=l"(d) : "l"(a), "l"(b), "l"(c));
    return d;
}
__device__ __forceinline__ u64 add2(u64 a, u64 b) {
    u64 d;
    asm("add.rn.f32x2 %0, %1, %2;" : "=l"(d) : "l"(a), "l"(b));
    return d;
}
__device__ __forceinline__ float f2lo(u64 a) { return __uint_as_float((unsigned)a); }
__device__ __forceinline__ float f2hi(u64 a) { return __uint_as_float((unsigned)(a >> 32)); }

__device__ __forceinline__ float ex2a(float x) { float y; asm("ex2.approx.f32 %0, %1;" : "=f"(y) : "f"(x)); return y; }
__device__ __forceinline__ float rcpa(float x) { float y; asm("rcp.approx.f32 %0, %1;" : "=f"(y) : "f"(x)); return y; }

// sigmoid(x) = 1/(1 + 2^(-x*log2e)); ~1e-7 accurate
__device__ __forceinline__ float sigm(float x) {
    return rcpa(1.0f + ex2a(-1.4426950408889634f * x));
}
// tanh(x) = 1 - 2/(1 + 2^(2x*log2e)); ~1e-7 accurate
__device__ __forceinline__ float tanh_(float x) {
    return fmaf(-2.0f, rcpa(1.0f + ex2a(2.8853900817779268f * x)), 1.0f);
}

// Shared-memory layout shared by both NB paths
struct Sh {
    float in[2][TIN];                        // staged input rows
    alignas(16) float h1[2][Hh];
    alignas(16) float h2[2][Hh];
    float zA[2][4 * Hh];                     // layer-1 pre-activations
    float zB[2][4 * Hh];                     // layer-2 pre-activations
    alignas(16) float wl[Hh];                // W_lin copy
    float wih1[4 * Hh];                      // W_ih1 copy (gen x-fold)
};

// Full scan for one block handling NB batch elements (champion R9 structure).
template <int NB>
__device__ __forceinline__ void run_scan(
    Sh& sh, const int r, const int b0,
    const float* __restrict__ input,
    const float wih1, const float bb1, const float bb2, const float blin,
    const u64* whh1p, const u64* wih2p, const u64* whh2p,
    float* __restrict__ out)
{
    const int lane = r & 31;
    const bool front = (r < NB * Hh);        // combine-duty threads
    const int ce = r >> 5;                   // element owned (valid when front)
    const int cj = lane;                     // hidden unit owned

    // ---- Stage input rows ----
#pragma unroll
    for (int e = 0; e < NB; e++)
        for (int t = r; t < TIN; t += 128)
            sh.in[e][t] = input[(b0 + e) * TIN + t];

    if (front) { sh.h1[ce][cj] = 0.0f; sh.h2[ce][cj] = 0.0f; }
    float c1 = 0.0f, c2 = 0.0f;              // cell states of (ce,cj), front only
    __syncthreads();

    // ================= Teacher-forced phase: 3 barriers/step, head deferred =================
#pragma unroll 1
    for (int t = 0; t < TIN; t++) {
        // P1: layer-1 gate pre-activations (all threads)
#pragma unroll
        for (int e = 0; e < NB; e++) {
            float x = sh.in[e][t];
            const ulonglong2* hp = (const ulonglong2*)sh.h1[e];   // broadcast LDS.128
            u64 a0 = 0ull, a1 = 0ull;
#pragma unroll
            for (int i = 0; i < 8; i++) {
                ulonglong2 hv = hp[i];
                a0 = fma2(whh1p[2 * i],     hv.x, a0);
                a1 = fma2(whh1p[2 * i + 1], hv.y, a1);
            }
            u64 s = add2(a0, a1);
            sh.zA[e][r] = fmaf(wih1, x, bb1) + (f2lo(s) + f2hi(s));
        }
        __syncthreads();                 // A

        // P2: layer-1 combine (front threads)
        if (front) {
            float zi = sh.zA[ce][cj],          zf = sh.zA[ce][Hh + cj];
            float zg = sh.zA[ce][2 * Hh + cj], zo = sh.zA[ce][3 * Hh + cj];
            float cn = fmaf(sigm(zf), c1, sigm(zi) * tanh_(zg));
            c1 = cn;
            sh.h1[ce][cj] = sigm(zo) * tanh_(cn);
        }
        __syncthreads();                 // B

        // P3: layer-2 gate pre-activations (all threads)
#pragma unroll
        for (int e = 0; e < NB; e++) {
            const ulonglong2* h1p = (const ulonglong2*)sh.h1[e];
            const ulonglong2* h2p = (const ulonglong2*)sh.h2[e];
            u64 a0 = 0ull, a1 = 0ull, a2 = 0ull, a3 = 0ull;
#pragma unroll
            for (int i = 0; i < 8; i++) {
                ulonglong2 hv1 = h1p[i];
                ulonglong2 hv2 = h2p[i];
                a0 = fma2(wih2p[2 * i],     hv1.x, a0);
                a1 = fma2(wih2p[2 * i + 1], hv1.y, a1);
                a2 = fma2(whh2p[2 * i],     hv2.x, a2);
                a3 = fma2(whh2p[2 * i + 1], hv2.y, a3);
            }
            u64 s = add2(add2(a0, a1), add2(a2, a3));
            sh.zB[e][r] = bb2 + (f2lo(s) + f2hi(s));
        }
        __syncthreads();                 // C

        // P4: layer-2 combine + h2 history store; no barrier (flows into P1)
        if (front) {
            float zi = sh.zB[ce][cj],          zf = sh.zB[ce][Hh + cj];
            float zg = sh.zB[ce][2 * Hh + cj], zo = sh.zB[ce][3 * Hh + cj];
            float cn = fmaf(sigm(zf), c2, sigm(zi) * tanh_(zg));
            c2 = cn;
            float hn = sigm(zo) * tanh_(cn);
            sh.h2[ce][cj] = hn;
            H2g[((size_t)(b0 + ce) * TIN + t) * Hh + cj] = hn;   // coalesced
        }
    }

    // ================= Gen phase: 3 barriers/step, feedback recomputed in P2 =================
#pragma unroll 1
    for (int t = TIN; t < STEPS; t++) {
        // P1: x-independent hh1 partial
#pragma unroll
        for (int e = 0; e < NB; e++) {
            const ulonglong2* hp = (const ulonglong2*)sh.h1[e];
            u64 a0 = 0ull, a1 = 0ull;
#pragma unroll
            for (int i = 0; i < 8; i++) {
                ulonglong2 hv = hp[i];
                a0 = fma2(whh1p[2 * i],     hv.x, a0);
                a1 = fma2(whh1p[2 * i + 1], hv.y, a1);
            }
            u64 s = add2(a0, a1);
            sh.zA[e][r] = bb1 + (f2lo(s) + f2hi(s));
        }
        __syncthreads();                 // A: z1-partials ready; h2(t-1) final

        // P2 (front): x = W_lin@h2(t-1)+b, emit out[t-1], fold, combine L1
        if (front) {
            const ulonglong2* wp = (const ulonglong2*)sh.wl;
            const ulonglong2* hp = (const ulonglong2*)sh.h2[ce];
            u64 a0 = 0ull, a1 = 0ull;
#pragma unroll
            for (int i = 0; i < 8; i++) {
                ulonglong2 wv = wp[i];
                ulonglong2 hv = hp[i];
                a0 = fma2(wv.x, hv.x, a0);
                a1 = fma2(wv.y, hv.y, a1);
            }
            u64 sx = add2(a0, a1);
            float x = (f2lo(sx) + f2hi(sx)) + blin;              // == out(t-1)
            if (cj == 0) out[(size_t)(b0 + ce) * STEPS + (t - 1)] = x;

            float zi = fmaf(sh.wih1[cj],          x, sh.zA[ce][cj]);
            float zf = fmaf(sh.wih1[Hh + cj],     x, sh.zA[ce][Hh + cj]);
            float zg = fmaf(sh.wih1[2 * Hh + cj], x, sh.zA[ce][2 * Hh + cj]);
            float zo = fmaf(sh.wih1[3 * Hh + cj], x, sh.zA[ce][3 * Hh + cj]);
            float cn = fmaf(sigm(zf), c1, sigm(zi) * tanh_(zg));
            c1 = cn;
            sh.h1[ce][cj] = sigm(zo) * tanh_(cn);
        }
        __syncthreads();                 // B

        // P3: layer-2 dots
#pragma unroll
        for (int e = 0; e < NB; e++) {
            const ulonglong2* h1p = (const ulonglong2*)sh.h1[e];
            const ulonglong2* h2p = (const ulonglong2*)sh.h2[e];
            u64 a0 = 0ull, a1 = 0ull, a2 = 0ull, a3 = 0ull;
#pragma unroll
            for (int i = 0; i < 8; i++) {
                ulonglong2 hv1 = h1p[i];
                ulonglong2 hv2 = h2p[i];
                a0 = fma2(wih2p[2 * i],     hv1.x, a0);
                a1 = fma2(wih2p[2 * i + 1], hv1.y, a1);
                a2 = fma2(whh2p[2 * i],     hv2.x, a2);
                a3 = fma2(whh2p[2 * i + 1], hv2.y, a3);
            }
            u64 s = add2(add2(a0, a1), add2(a2, a3));
            sh.zB[e][r] = bb2 + (f2lo(s) + f2hi(s));
        }
        __syncthreads();                 // C

        // P4 (front): combine L2 -> h2(t); no barrier
        if (front) {
            float zi = sh.zB[ce][cj],          zf = sh.zB[ce][Hh + cj];
            float zg = sh.zB[ce][2 * Hh + cj], zo = sh.zB[ce][3 * Hh + cj];
            float cn = fmaf(sigm(zf), c2, sigm(zi) * tanh_(zg));
            c2 = cn;
            sh.h2[ce][cj] = sigm(zo) * tanh_(cn);
        }
    }

    // Final output: out[STEPS-1] = W_lin @ h2(final) + b_lin
    __syncthreads();
    if (front && cj == 0) {
        const ulonglong2* wp = (const ulonglong2*)sh.wl;
        const ulonglong2* hp = (const ulonglong2*)sh.h2[ce];
        u64 a0 = 0ull, a1 = 0ull;
#pragma unroll
        for (int i = 0; i < 8; i++) {
            ulonglong2 wv = wp[i];
            ulonglong2 hv = hp[i];
            a0 = fma2(wv.x, hv.x, a0);
            a1 = fma2(wv.y, hv.y, a1);
        }
        u64 sx = add2(a0, a1);
        out[(size_t)(b0 + ce) * STEPS + (STEPS - 1)] = (f2lo(sx) + f2hi(sx)) + blin;
    }
}

__global__ __launch_bounds__(128, 4) void lstm_seq_kernel(
    const float* __restrict__ input,
    const float* __restrict__ W_ih1, const float* __restrict__ W_hh1,
    const float* __restrict__ b_ih1, const float* __restrict__ b_hh1,
    const float* __restrict__ W_ih2, const float* __restrict__ W_hh2,
    const float* __restrict__ b_ih2, const float* __restrict__ b_hh2,
    const float* __restrict__ W_lin, const float* __restrict__ b_lin,
    float* __restrict__ out)
{
    __shared__ Sh sh;

    const int r   = threadIdx.x;
    const int bid = blockIdx.x;

    // ---- Weights into registers (identical for both paths) ----
    const float wih1 = W_ih1[r];
    const float bb1  = b_ih1[r] + b_hh1[r];
    const float bb2  = b_ih2[r] + b_hh2[r];
    const float blin = b_lin[0];

    u64 whh1p[Hh / 2], wih2p[Hh / 2], whh2p[Hh / 2];
    {
        const u64* p1 = (const u64*)(W_hh1 + r * Hh);  // rows are 128B -> 8B aligned
        const u64* p2 = (const u64*)(W_ih2 + r * Hh);
        const u64* p3 = (const u64*)(W_hh2 + r * Hh);
#pragma unroll
        for (int i = 0; i < Hh / 2; i++) { whh1p[i] = p1[i]; wih2p[i] = p2[i]; whh2p[i] = p3[i]; }
    }
    if (r < Hh) sh.wl[r] = W_lin[r];
    sh.wih1[r] = wih1;   // covered by first __syncthreads inside run_scan

    // Mixed-EPB mapping: bids 0..G2-1 handle 2 elements; G2..GRID-1 handle 1.
    // With LUT placement each SM hosts {s, s+148, s+296, s+444}: the +444 block
    // (and for 12 SMs the +296 block) is single-element -> 7 (or 6) elements/SM.
    if (bid < G2) {
        run_scan<2>(sh, r, bid * 2, input, wih1, bb1, bb2, blin,
                    whh1p, wih2p, whh2p, out);
    } else {
        run_scan<1>(sh, r, 2 * G2 + (bid - G2), input, wih1, bb1, bb2, blin,
                    whh1p, wih2p, whh2p, out);
    }
}

// Apply linear head to stored TF h2 history: out[b][t] = W_lin @ H2g[b][t] + b_lin
__global__ __launch_bounds__(256) void head_kernel(
    const float* __restrict__ W_lin, const float* __restrict__ b_lin,
    float* __restrict__ out)
{
    const int b = blockIdx.x;
    float4 wv[8];
    const float4* wp = (const float4*)W_lin;
#pragma unroll
    for (int i = 0; i < 8; i++) wv[i] = wp[i];
    const float bl = b_lin[0];

    for (int t = threadIdx.x; t < TIN; t += 256) {
        const float4* hp = (const float4*)(H2g + ((size_t)b * TIN + t) * Hh);
        float acc = bl;
#pragma unroll
        for (int i = 0; i < 8; i++) {
            float4 h = hp[i];
            acc += wv[i].x * h.x + wv[i].y * h.y + wv[i].z * h.z + wv[i].w * h.w;
        }
        out[(size_t)b * STEPS + t] = acc;
    }
}

extern "C" void kernel_launch(void* const* d_in, const int* in_sizes, int n_in,
                              void* d_out, int out_size) {
    const float* input = (const float*)d_in[0];
    const float* W_ih1 = (const float*)d_in[1];
    const float* W_hh1 = (const float*)d_in[2];
    const float* b_ih1 = (const float*)d_in[3];
    const float* b_hh1 = (const float*)d_in[4];
    const float* W_ih2 = (const float*)d_in[5];
    const float* W_hh2 = (const float*)d_in[6];
    const float* b_ih2 = (const float*)d_in[7];
    const float* b_hh2 = (const float*)d_in[8];
    const float* W_lin = (const float*)d_in[9];
    const float* b_lin = (const float*)d_in[10];
    float* out = (float*)d_out;

    lstm_seq_kernel<<<GRID, 128>>>(input, W_ih1, W_hh1, b_ih1, b_hh1,
                                   W_ih2, W_hh2, b_ih2, b_hh2,
                                   W_lin, b_lin, out);
    head_kernel<<<BATCH, 256>>>(W_lin, b_lin, out);
}